// round 5
// baseline (speedup 1.0000x reference)
#include <cuda_runtime.h>
#include <cuda_bf16.h>

// LogSignature depth=4 of path (B=128, T=512, C=8).
// Output per batch: [L1(8) | L2(64) | L3(512) | L4(4096)] = 4680 floats.
//
// ROUND 5 (re-bench of R4; infra failure last round): 4-way time split.
//   Kernel 1 (scan): grid = 256 = 2 CTAs per batch. CTA (b,h) scans quarters
//   2h and 2h+1 (128 steps each) in the two lanes of packed f32x2 ops,
//   combines its lanes with one Chen product, and writes the half-signature
//   to a __device__ scratch. __launch_bounds__(512,2) caps regs at 64 so two
//   CTAs co-reside per SM (8 warps/SMSP) to hide LDS/FMA latency.
//   Kernel 2 (combine): grid = 128. Chen-combines the two halves and applies
//   the closed-form truncated log, writing the final output.

#define BATCH 128
#define TLEN  512
#define CH    8
#define NSTEP (TLEN - 1)      // 511
#define NQ    128             // steps per quarter (packed loop length)
#define OUT_STRIDE 4680       // 8 + 64 + 512 + 4096
#define OFF_L2 8
#define OFF_L3 72
#define OFF_L4 584

typedef unsigned long long u64;

__device__ float g_scratch[2 * BATCH * OUT_STRIDE];   // 4.79 MB

__device__ __forceinline__ u64 ffma2(u64 a, u64 b, u64 c) {
    u64 d; asm("fma.rn.f32x2 %0, %1, %2, %3;" : "=l"(d) : "l"(a), "l"(b), "l"(c)); return d;
}
__device__ __forceinline__ u64 fmul2(u64 a, u64 b) {
    u64 d; asm("mul.rn.f32x2 %0, %1, %2;" : "=l"(d) : "l"(a), "l"(b)); return d;
}
__device__ __forceinline__ u64 fadd2(u64 a, u64 b) {
    u64 d; asm("add.rn.f32x2 %0, %1, %2;" : "=l"(d) : "l"(a), "l"(b)); return d;
}
__device__ __forceinline__ u64 pack2(float x, float y) {
    u64 d; asm("mov.b64 %0, {%1, %2};" : "=l"(d) : "f"(x), "f"(y)); return d;
}
__device__ __forceinline__ void unpack2(u64 a, float& x, float& y) {
    asm("mov.b64 {%0, %1}, %2;" : "=f"(x), "=f"(y) : "l"(a));
}

// packed constants (both lanes equal): bit patterns of 0.5f, 1/6f, 1/24f
#define C2P 0x3F0000003F000000ULL
#define C3P 0x3E2AAAAB3E2AAAABULL
#define C4P 0x3D2AAAAB3D2AAAABULL

// ---------------------------------------------------------------------------
// Kernel 1: packed Chen scan over two quarters + lane combine -> scratch
// ---------------------------------------------------------------------------
__global__ void __launch_bounds__(512, 2)
logsig_scan(const float* __restrict__ path)
{
    __shared__ __align__(16) u64 s_dx2[NQ * CH];      // 8 KB
    __shared__ float sB1[8], sB2[64], sB3[512];       // lane-B signature

    const int b   = blockIdx.x >> 1;
    const int h   = blockIdx.x & 1;
    const int tid = threadIdx.x;
    const float* p = path + (size_t)b * TLEN * CH;

    const int baseA = (2 * h) * NQ * CH;      // element offset of quarter-A steps
    const int baseB = (2 * h + 1) * NQ * CH;  // element offset of quarter-B steps

    // Build interleaved increments: s_dx2[t*8+c] = (dxA, dxB)
    for (int idx = tid; idx < NQ * CH; idx += 512) {
        const float dxA = p[baseA + idx + CH] - p[baseA + idx];
        float dxB = 0.0f;
        if (baseB + idx < NSTEP * CH)          // only the global last step (511) is padding
            dxB = p[baseB + idx + CH] - p[baseB + idx];
        s_dx2[idx] = pack2(dxA, dxB);
    }
    __syncthreads();

    const int i = tid >> 6;
    const int j = (tid >> 3) & 7;
    const int k = tid & 7;

    u64 r1 = 0, r2 = 0, r3 = 0;
    u64 a0 = 0, a1 = 0, a2 = 0, a3 = 0, a4 = 0, a5 = 0, a6 = 0, a7 = 0;

    const u64 c2 = C2P, c3 = C3P, c4 = C4P;

    #pragma unroll 2
    for (int t = 0; t < NQ; ++t) {
        const u64* d = &s_dx2[t * CH];
        const ulonglong2 q0 = *(const ulonglong2*)(d + 0);
        const ulonglong2 q1 = *(const ulonglong2*)(d + 2);
        const ulonglong2 q2 = *(const ulonglong2*)(d + 4);
        const ulonglong2 q3 = *(const ulonglong2*)(d + 6);
        const u64 di = d[i];
        const u64 dj = d[j];
        const u64 dk = d[k];

        const u64 djk  = fmul2(dj, dk);
        const u64 dijk = fmul2(di, djk);
        const u64 u = fmul2(r2, dk);     // OLD r2
        const u64 v = fmul2(r1, djk);    // OLD r1

        // level-4 rank-1 update
        u64 g = ffma2(c2, u, r3);
        g = ffma2(c3, v, g);
        g = ffma2(c4, dijk, g);
        a0 = ffma2(g, q0.x, a0);
        a1 = ffma2(g, q0.y, a1);
        a2 = ffma2(g, q1.x, a2);
        a3 = ffma2(g, q1.y, a3);
        a4 = ffma2(g, q2.x, a4);
        a5 = ffma2(g, q2.y, a5);
        a6 = ffma2(g, q3.x, a6);
        a7 = ffma2(g, q3.y, a7);

        // level-3
        r3 = fadd2(r3, u);
        r3 = ffma2(c2, v, r3);
        r3 = ffma2(c3, dijk, r3);

        // level-2: r2 += dj * (r1 + 0.5*di)
        const u64 tmp = ffma2(c2, di, r1);
        r2 = ffma2(dj, tmp, r2);

        // level-1
        r1 = fadd2(r1, di);
    }

    // ---- unpack lanes: A = quarter 2h, B = quarter 2h+1 ----
    float A1, B1, A2, B2, A3, B3;
    unpack2(r1, A1, B1);
    unpack2(r2, A2, B2);
    unpack2(r3, A3, B3);
    float aA[8], aB[8];
    unpack2(a0, aA[0], aB[0]); unpack2(a1, aA[1], aB[1]);
    unpack2(a2, aA[2], aB[2]); unpack2(a3, aA[3], aB[3]);
    unpack2(a4, aA[4], aB[4]); unpack2(a5, aA[5], aB[5]);
    unpack2(a6, aA[6], aB[6]); unpack2(a7, aA[7], aB[7]);

    sB3[tid] = B3;
    if (k == 0)          sB2[i * 8 + j] = B2;
    if ((tid & 63) == 0) sB1[i] = B1;
    __syncthreads();

    // ---- Chen combine lanes: H = A (x) B ----
    const float c1v = A1 + B1;
    const float c2v = A2 + B2 + A1 * sB1[j];
    const float c3v = A3 + B3 + A1 * sB2[j * 8 + k] + A2 * sB1[k];

    float* gs = g_scratch + (size_t)blockIdx.x * OUT_STRIDE;

    {
        const float* b3row = &sB3[(j * 8 + k) * 8];
        const float* b2row = &sB2[k * 8];
        float4 w0, w1;
        float w[8];
        #pragma unroll
        for (int l = 0; l < 8; ++l) {
            float t4 = aA[l] + aB[l];
            t4 = fmaf(A3, sB1[l], t4);
            t4 = fmaf(A2, b2row[l], t4);
            t4 = fmaf(A1, b3row[l], t4);
            w[l] = t4;
        }
        w0.x = w[0]; w0.y = w[1]; w0.z = w[2]; w0.w = w[3];
        w1.x = w[4]; w1.y = w[5]; w1.z = w[6]; w1.w = w[7];
        *(float4*)(&gs[OFF_L4 + tid * 8])     = w0;
        *(float4*)(&gs[OFF_L4 + tid * 8 + 4]) = w1;
    }

    gs[OFF_L3 + tid] = c3v;
    if (k == 0)          gs[OFF_L2 + i * 8 + j] = c2v;
    if ((tid & 63) == 0) gs[i] = c1v;
}

// ---------------------------------------------------------------------------
// Kernel 2: combine the two half-signatures + closed-form log
// ---------------------------------------------------------------------------
__global__ void __launch_bounds__(512, 1)
logsig_combine(float* __restrict__ out)
{
    __shared__ float sB[584];   // H1 levels 1..3: [L1 8 | L2 64 | L3 512]
    __shared__ float sc[584];   // combined levels 1..3

    const int b   = blockIdx.x;
    const int tid = threadIdx.x;
    const float* g0 = g_scratch + (size_t)(2 * b)     * OUT_STRIDE;
    const float* g1 = g_scratch + (size_t)(2 * b + 1) * OUT_STRIDE;

    for (int idx = tid; idx < 584; idx += 512) sB[idx] = g1[idx];
    __syncthreads();

    const int i = tid >> 6;
    const int j = (tid >> 3) & 7;
    const int k = tid & 7;

    const float A1 = g0[i];
    const float A2 = g0[OFF_L2 + i * 8 + j];
    const float A3 = g0[OFF_L3 + tid];
    const float4 a40 = *(const float4*)(g0 + OFF_L4 + tid * 8);
    const float4 a41 = *(const float4*)(g0 + OFF_L4 + tid * 8 + 4);
    const float4 b40 = *(const float4*)(g1 + OFF_L4 + tid * 8);
    const float4 b41 = *(const float4*)(g1 + OFF_L4 + tid * 8 + 4);

    // ---- Chen combine: S = H0 (x) H1 ----
    const float c1v = A1 + sB[i];
    const float c2v = A2 + sB[8 + i * 8 + j] + A1 * sB[j];
    const float c3v = A3 + sB[72 + tid] + A1 * sB[8 + j * 8 + k] + A2 * sB[k];

    float w[8];
    {
        const float aA[8] = {a40.x, a40.y, a40.z, a40.w, a41.x, a41.y, a41.z, a41.w};
        const float aB[8] = {b40.x, b40.y, b40.z, b40.w, b41.x, b41.y, b41.z, b41.w};
        const float* b3row = &sB[72 + (j * 8 + k) * 8];
        const float* b2row = &sB[8 + k * 8];
        #pragma unroll
        for (int l = 0; l < 8; ++l) {
            float t4 = aA[l] + aB[l];
            t4 = fmaf(A3, sB[l], t4);
            t4 = fmaf(A2, b2row[l], t4);
            t4 = fmaf(A1, b3row[l], t4);
            w[l] = t4;
        }
    }

    sc[72 + tid] = c3v;
    if (k == 0)          sc[8 + i * 8 + j] = c2v;
    if ((tid & 63) == 0) sc[i] = c1v;
    __syncthreads();

    // ---- closed-form log(1+x) truncated at depth 4 ----
    const float si = sc[i];
    const float sj = sc[j];
    const float sk = sc[k];
    const float s2ij  = c2v;
    const float s2jk  = sc[8 + j * 8 + k];
    const float s3ijk = c3v;

    const float cross = fmaf(si, s2jk, s2ij * sk);
    const float sss   = si * sj * sk;

    const float P = fmaf(1.0f / 3.0f, cross, -0.5f * s3ijk) - 0.25f * sss;
    const float Q = fmaf(1.0f / 3.0f, si * sj, -0.5f * s2ij);
    const float R = -0.5f * si;

    float* ob = out + (size_t)b * OUT_STRIDE;

    {
        const float* s3row = &sc[72 + (j * 8 + k) * 8];
        const float* s2row = &sc[8 + k * 8];
        float4 w0, w1;
        w0.x = w[0] + P * sc[0] + Q * s2row[0] + R * s3row[0];
        w0.y = w[1] + P * sc[1] + Q * s2row[1] + R * s3row[1];
        w0.z = w[2] + P * sc[2] + Q * s2row[2] + R * s3row[2];
        w0.w = w[3] + P * sc[3] + Q * s2row[3] + R * s3row[3];
        w1.x = w[4] + P * sc[4] + Q * s2row[4] + R * s3row[4];
        w1.y = w[5] + P * sc[5] + Q * s2row[5] + R * s3row[5];
        w1.z = w[6] + P * sc[6] + Q * s2row[6] + R * s3row[6];
        w1.w = w[7] + P * sc[7] + Q * s2row[7] + R * s3row[7];
        *(float4*)(&ob[OFF_L4 + tid * 8])     = w0;
        *(float4*)(&ob[OFF_L4 + tid * 8 + 4]) = w1;
    }

    ob[OFF_L3 + tid] = fmaf(1.0f / 3.0f, sss, fmaf(-0.5f, cross, s3ijk));

    if (k == 0)
        ob[OFF_L2 + i * 8 + j] = fmaf(-0.5f * si, sj, c2v);

    if ((tid & 63) == 0)
        ob[i] = c1v;
}

extern "C" void kernel_launch(void* const* d_in, const int* in_sizes, int n_in,
                              void* d_out, int out_size)
{
    const float* path = (const float*)d_in[0];
    float* out = (float*)d_out;
    logsig_scan<<<2 * BATCH, 512>>>(path);
    logsig_combine<<<BATCH, 512>>>(out);
}

// round 6
// speedup vs baseline: 1.0871x; 1.0871x over previous
#include <cuda_runtime.h>
#include <cuda_bf16.h>
#include <cstdint>

// LogSignature depth=4 of path (B=128, T=512, C=8).
// Output per batch: [L1(8) | L2(64) | L3(512) | L4(4096)] = 4680 floats.
//
// ROUND 6: fused cluster kernel. grid = 256, cluster(2): the two CTAs of a
// batch each scan two quarters (128 steps) in the two lanes of packed f32x2
// ops (#pragma unroll 1 to avoid the 64-reg spills seen under unroll 2),
// lane-combine to a half-signature, publish it in SMEM, exchange via DSMEM
// after a cluster barrier, then Chen-combine + closed-form log in the tail.
// CTA rank r writes L4 columns l in [4r,4r+4); rank 0 writes L1..L3.

#define BATCH 128
#define TLEN  512
#define CH    8
#define NSTEP (TLEN - 1)      // 511
#define NQ    128             // steps per quarter (packed loop length)
#define OUT_STRIDE 4680
#define OFF_L2 8
#define OFF_L3 72
#define OFF_L4 584

typedef unsigned long long u64;

__device__ __forceinline__ u64 ffma2(u64 a, u64 b, u64 c) {
    u64 d; asm("fma.rn.f32x2 %0, %1, %2, %3;" : "=l"(d) : "l"(a), "l"(b), "l"(c)); return d;
}
__device__ __forceinline__ u64 fmul2(u64 a, u64 b) {
    u64 d; asm("mul.rn.f32x2 %0, %1, %2;" : "=l"(d) : "l"(a), "l"(b)); return d;
}
__device__ __forceinline__ u64 fadd2(u64 a, u64 b) {
    u64 d; asm("add.rn.f32x2 %0, %1, %2;" : "=l"(d) : "l"(a), "l"(b)); return d;
}
__device__ __forceinline__ u64 pack2(float x, float y) {
    u64 d; asm("mov.b64 %0, {%1, %2};" : "=l"(d) : "f"(x), "f"(y)); return d;
}
__device__ __forceinline__ void unpack2(u64 a, float& x, float& y) {
    asm("mov.b64 {%0, %1}, %2;" : "=f"(x), "=f"(y) : "l"(a));
}
__device__ __forceinline__ uint32_t smem_u32(const void* p) {
    uint32_t a;
    asm("{ .reg .u64 t; cvta.to.shared.u64 t, %1; cvt.u32.u64 %0, t; }" : "=r"(a) : "l"(p));
    return a;
}
__device__ __forceinline__ uint32_t mapa_rank(uint32_t addr, uint32_t rank) {
    uint32_t r; asm("mapa.shared::cluster.u32 %0, %1, %2;" : "=r"(r) : "r"(addr), "r"(rank));
    return r;
}
__device__ __forceinline__ float4 ld_dsmem_v4(uint32_t addr) {
    float4 v;
    asm volatile("ld.shared::cluster.v4.f32 {%0,%1,%2,%3}, [%4];"
                 : "=f"(v.x), "=f"(v.y), "=f"(v.z), "=f"(v.w) : "r"(addr));
    return v;
}
__device__ __forceinline__ void cluster_sync_() {
    asm volatile("barrier.cluster.arrive.aligned;" ::: "memory");
    asm volatile("barrier.cluster.wait.aligned;" ::: "memory");
}

// packed constants (both lanes): 0.5f, 1/6f, 1/24f
#define C2P 0x3F0000003F000000ULL
#define C3P 0x3E2AAAAB3E2AAAABULL
#define C4P 0x3D2AAAAB3D2AAAABULL

__global__ void __launch_bounds__(512, 2) __cluster_dims__(2, 1, 1)
logsig_fused(const float* __restrict__ path, float* __restrict__ out)
{
    __shared__ __align__(16) u64 s_dx2[NQ * CH];          // 8 KB
    __shared__ float sB1[8], sB2[64], sB3[512];           // lane-B levels (intra-CTA)
    __shared__ __align__(16) float sH[584];               // own half levels 1..3
    __shared__ __align__(16) float sH4[4096];             // own half L4 (16 KB)
    __shared__ __align__(16) float sP[584];               // peer half levels 1..3
    __shared__ float sc[584];                             // combined levels 1..3

    const int b    = blockIdx.x >> 1;
    const int rank = blockIdx.x & 1;                      // cluster CTA rank
    const int tid  = threadIdx.x;
    const float* p = path + (size_t)b * TLEN * CH;

    const int baseA = (2 * rank) * NQ * CH;
    const int baseB = (2 * rank + 1) * NQ * CH;

    // Build interleaved increments: s_dx2[t*8+c] = (dx quarter 2r, dx quarter 2r+1)
    for (int idx = tid; idx < NQ * CH; idx += 512) {
        const float dxA = p[baseA + idx + CH] - p[baseA + idx];
        float dxB = 0.0f;
        if (baseB + idx < NSTEP * CH)      // only global step 511 is padding
            dxB = p[baseB + idx + CH] - p[baseB + idx];
        s_dx2[idx] = pack2(dxA, dxB);
    }
    __syncthreads();

    const int i = tid >> 6;
    const int j = (tid >> 3) & 7;
    const int k = tid & 7;

    u64 r1 = 0, r2 = 0, r3 = 0;
    u64 a0 = 0, a1 = 0, a2 = 0, a3 = 0, a4 = 0, a5 = 0, a6 = 0, a7 = 0;

    const u64 c2 = C2P, c3 = C3P, c4 = C4P;

    #pragma unroll 1
    for (int t = 0; t < NQ; ++t) {
        const u64* d = &s_dx2[t * CH];
        const ulonglong2 q0 = *(const ulonglong2*)(d + 0);
        const ulonglong2 q1 = *(const ulonglong2*)(d + 2);
        const ulonglong2 q2 = *(const ulonglong2*)(d + 4);
        const ulonglong2 q3 = *(const ulonglong2*)(d + 6);
        const u64 di = d[i];
        const u64 dj = d[j];
        const u64 dk = d[k];

        const u64 djk  = fmul2(dj, dk);
        const u64 dijk = fmul2(di, djk);
        const u64 u = fmul2(r2, dk);     // OLD r2
        const u64 v = fmul2(r1, djk);    // OLD r1

        // level-4 rank-1 update
        u64 g = ffma2(c2, u, r3);
        g = ffma2(c3, v, g);
        g = ffma2(c4, dijk, g);
        a0 = ffma2(g, q0.x, a0);
        a1 = ffma2(g, q0.y, a1);
        a2 = ffma2(g, q1.x, a2);
        a3 = ffma2(g, q1.y, a3);
        a4 = ffma2(g, q2.x, a4);
        a5 = ffma2(g, q2.y, a5);
        a6 = ffma2(g, q3.x, a6);
        a7 = ffma2(g, q3.y, a7);

        // level-3
        r3 = fadd2(r3, u);
        r3 = ffma2(c2, v, r3);
        r3 = ffma2(c3, dijk, r3);

        // level-2: r2 += dj * (r1 + 0.5*di)
        const u64 tmp = ffma2(c2, di, r1);
        r2 = ffma2(dj, tmp, r2);

        // level-1
        r1 = fadd2(r1, di);
    }

    // ---- unpack lanes: A = quarter 2r, B = quarter 2r+1 ----
    float A1, B1, A2, B2, A3, B3;
    unpack2(r1, A1, B1);
    unpack2(r2, A2, B2);
    unpack2(r3, A3, B3);
    float aA[8], aB[8];
    unpack2(a0, aA[0], aB[0]); unpack2(a1, aA[1], aB[1]);
    unpack2(a2, aA[2], aB[2]); unpack2(a3, aA[3], aB[3]);
    unpack2(a4, aA[4], aB[4]); unpack2(a5, aA[5], aB[5]);
    unpack2(a6, aA[6], aB[6]); unpack2(a7, aA[7], aB[7]);

    sB3[tid] = B3;
    if (k == 0)          sB2[i * 8 + j] = B2;
    if ((tid & 63) == 0) sB1[i] = B1;
    __syncthreads();

    // ---- Chen combine lanes -> this CTA's half-signature H_r ----
    const float h1v = A1 + B1;
    const float h2v = A2 + B2 + A1 * sB1[j];
    const float h3v = A3 + B3 + A1 * sB2[j * 8 + k] + A2 * sB1[k];

    float w[8];
    {
        const float* b3row = &sB3[(j * 8 + k) * 8];
        const float* b2row = &sB2[k * 8];
        #pragma unroll
        for (int l = 0; l < 8; ++l) {
            float t4 = aA[l] + aB[l];
            t4 = fmaf(A3, sB1[l], t4);
            t4 = fmaf(A2, b2row[l], t4);
            t4 = fmaf(A1, b3row[l], t4);
            w[l] = t4;
        }
    }

    // ---- publish own half in SMEM ----
    sH[72 + tid] = h3v;
    if (k == 0)          sH[8 + (tid >> 3)] = h2v;
    if ((tid & 63) == 0) sH[i] = h1v;
    {
        float4 w0 = {w[0], w[1], w[2], w[3]};
        float4 w1 = {w[4], w[5], w[6], w[7]};
        *(float4*)(&sH4[tid * 8])     = w0;
        *(float4*)(&sH4[tid * 8 + 4]) = w1;
    }

    // barrier.cluster orders the SMEM writes before peer DSMEM reads
    cluster_sync_();

    // ---- fetch peer half via DSMEM ----
    const uint32_t peer = (uint32_t)(rank ^ 1);
    {
        const uint32_t peerH = mapa_rank(smem_u32(sH), peer);
        for (int idx = tid; idx < 146; idx += 512)           // 584 floats = 146 float4
            *(float4*)(&sP[idx * 4]) = ld_dsmem_v4(peerH + idx * 16);
    }
    // peer L4 slice for this CTA's output columns l in [4*rank, 4*rank+4)
    float4 p4;
    {
        const uint32_t peer4 = mapa_rank(smem_u32(sH4), peer);
        p4 = ld_dsmem_v4(peer4 + (tid * 8 + 4 * rank) * 4);
    }
    __syncthreads();

    // ---- Chen combine: S = H0 (x) H1 (A-side = rank0 half, B-side = rank1 half) ----
    const float* Alev = (rank == 0) ? sH : sP;
    const float* Blev = (rank == 0) ? sP : sH;

    const float cA1 = Alev[i];
    const float cA2 = Alev[8 + (tid >> 3)];
    const float cA3 = Alev[72 + tid];

    const float c1v = cA1 + Blev[i];
    const float c2v = cA2 + Blev[8 + (tid >> 3)] + cA1 * Blev[j];
    const float c3v = cA3 + Blev[72 + tid] + cA1 * Blev[8 + j * 8 + k] + cA2 * Blev[k];

    // L4 combine for this CTA's 4 columns (l = 4*rank + m)
    float w4[4];
    {
        const float pv[4] = {p4.x, p4.y, p4.z, p4.w};
        #pragma unroll
        for (int m = 0; m < 4; ++m) {
            const int l = 4 * rank + m;
            const float A4v = (rank == 0) ? w[m] : pv[m];
            const float B4v = (rank == 0) ? pv[m] : w[4 + m];
            float t4 = A4v + B4v;
            t4 = fmaf(cA3, Blev[l], t4);
            t4 = fmaf(cA2, Blev[8 + k * 8 + l], t4);
            t4 = fmaf(cA1, Blev[72 + (j * 8 + k) * 8 + l], t4);
            w4[m] = t4;
        }
    }

    // publish combined levels for the log tail (CTA-local)
    sc[72 + tid] = c3v;
    if (k == 0)          sc[8 + (tid >> 3)] = c2v;
    if ((tid & 63) == 0) sc[i] = c1v;
    __syncthreads();

    // ---- closed-form log(1+x) truncated at depth 4 ----
    const float si = sc[i];
    const float sj = sc[j];
    const float sk = sc[k];
    const float s2ij  = c2v;
    const float s2jk  = sc[8 + j * 8 + k];
    const float s3ijk = c3v;

    const float cross = fmaf(si, s2jk, s2ij * sk);
    const float sss   = si * sj * sk;

    const float P = fmaf(1.0f / 3.0f, cross, -0.5f * s3ijk) - 0.25f * sss;
    const float Q = fmaf(1.0f / 3.0f, si * sj, -0.5f * s2ij);
    const float R = -0.5f * si;

    float* ob = out + (size_t)b * OUT_STRIDE;

    {
        float4 o;
        float ov[4];
        #pragma unroll
        for (int m = 0; m < 4; ++m) {
            const int l = 4 * rank + m;
            ov[m] = w4[m] + P * sc[l] + Q * sc[8 + k * 8 + l] + R * sc[72 + (j * 8 + k) * 8 + l];
        }
        o.x = ov[0]; o.y = ov[1]; o.z = ov[2]; o.w = ov[3];
        *(float4*)(&ob[OFF_L4 + tid * 8 + 4 * rank]) = o;
    }

    if (rank == 0) {
        ob[OFF_L3 + tid] = fmaf(1.0f / 3.0f, sss, fmaf(-0.5f, cross, s3ijk));
        if (k == 0)
            ob[OFF_L2 + i * 8 + j] = fmaf(-0.5f * si, sj, c2v);
        if ((tid & 63) == 0)
            ob[i] = c1v;
    }

    // keep peer SMEM alive until both CTAs are done
    cluster_sync_();
}

extern "C" void kernel_launch(void* const* d_in, const int* in_sizes, int n_in,
                              void* d_out, int out_size)
{
    const float* path = (const float*)d_in[0];
    float* out = (float*)d_out;
    logsig_fused<<<2 * BATCH, 512>>>(path, out);
}